// round 3
// baseline (speedup 1.0000x reference)
#include <cuda_runtime.h>
#include <math.h>

// Problem constants
#define BATCH 2
#define SEQ   2048
#define DM    1024
#define NH    16
#define DH    64
#define MROWS (BATCH*SEQ)   // 4096

// ---------------- scratch (no allocation allowed) ----------------
__device__ float g_Q[(size_t)BATCH*NH*SEQ*DH];   // [b][h][t][dh]
__device__ float g_K[(size_t)BATCH*NH*SEQ*DH];
__device__ float g_V[(size_t)BATCH*NH*SEQ*DH];
__device__ float g_A[(size_t)BATCH*SEQ*DM];      // attention out, [b][t][d]

// ---------------- GEMM: C = A(MxK) * W(NxK)^T + bias ----------------
// mode 0: plain row-major store C[m*N+n]
// mode 1: rotate_half pairs, store [b][h][t][dh]
// mode 2: no rotate, store [b][h][t][dh]
#define BM 64
#define BN 64
#define BK 16

__global__ __launch_bounds__(256)
void gemm_bias_kernel(const float* __restrict__ A, const float* __restrict__ W,
                      const float* __restrict__ bias, float* __restrict__ C,
                      int M, int N, int K, int mode)
{
    __shared__ float As[BK][BM];
    __shared__ float Bs[BK][BN];

    const int tid = threadIdx.x;          // 0..255
    const int tx  = tid & 15;             // 0..15 -> 4 cols each
    const int ty  = tid >> 4;             // 0..15 -> 4 rows each
    const int m0  = blockIdx.y * BM;
    const int n0  = blockIdx.x * BN;

    const int lr  = tid >> 2;             // 0..63 row within tile
    const int lk  = (tid & 3) * 4;        // k offset (float4)

    float acc[4][4] = {};

    for (int k0 = 0; k0 < K; k0 += BK) {
        float4 av = *(const float4*)(A + (size_t)(m0 + lr) * K + k0 + lk);
        float4 wv = *(const float4*)(W + (size_t)(n0 + lr) * K + k0 + lk);
        As[lk+0][lr] = av.x; As[lk+1][lr] = av.y; As[lk+2][lr] = av.z; As[lk+3][lr] = av.w;
        Bs[lk+0][lr] = wv.x; Bs[lk+1][lr] = wv.y; Bs[lk+2][lr] = wv.z; Bs[lk+3][lr] = wv.w;
        __syncthreads();

        #pragma unroll
        for (int k = 0; k < BK; k++) {
            float a[4], b[4];
            #pragma unroll
            for (int i = 0; i < 4; i++) a[i] = As[k][ty*4 + i];
            #pragma unroll
            for (int j = 0; j < 4; j++) b[j] = Bs[k][tx*4 + j];
            #pragma unroll
            for (int i = 0; i < 4; i++)
                #pragma unroll
                for (int j = 0; j < 4; j++)
                    acc[i][j] += a[i] * b[j];
        }
        __syncthreads();
    }

    const int nbase = n0 + tx*4;
    #pragma unroll
    for (int i = 0; i < 4; i++) {
        const int m = m0 + ty*4 + i;
        float y[4];
        #pragma unroll
        for (int j = 0; j < 4; j++) y[j] = acc[i][j] + bias[nbase + j];

        if (mode == 0) {
            float4 v = make_float4(y[0], y[1], y[2], y[3]);
            *(float4*)(C + (size_t)m * N + nbase) = v;
        } else {
            const int b = m / SEQ, t = m % SEQ;
            #pragma unroll
            for (int p = 0; p < 4; p += 2) {
                const int n  = nbase + p;
                const int h  = n >> 6;
                const int dh = n & 63;
                float o0, o1;
                if (mode == 1) { o0 = -y[p+1]; o1 = y[p]; }   // rotate_half
                else           { o0 =  y[p];  o1 = y[p+1]; }
                size_t base = (((size_t)(b*NH + h) * SEQ) + t) * DH + dh;
                C[base]     = o0;
                C[base + 1] = o1;
            }
        }
    }
}

// ---------------- attention: causal flash, 1 query row per thread ----------------
// grid: (SEQ/128, BATCH*NH), block: 128 threads
__global__ __launch_bounds__(128)
void attn_kernel(const float* __restrict__ Q, const float* __restrict__ K,
                 const float* __restrict__ V, float* __restrict__ O)
{
    __shared__ float Ksh[64][64];
    __shared__ float Vsh[64][64];

    const int bh  = blockIdx.y;             // 0..31
    const int row = blockIdx.x * 128 + threadIdx.x;

    const float* Qrow = Q + ((size_t)bh * SEQ + row) * DH;
    float q[DH], o[DH];
    #pragma unroll
    for (int d = 0; d < DH; d++) { q[d] = Qrow[d]; o[d] = 0.f; }

    float m = -INFINITY, l = 0.f;
    const int ntiles = 2 * blockIdx.x + 2;   // causal limit for this block

    const float* Kb = K + (size_t)bh * SEQ * DH;
    const float* Vb = V + (size_t)bh * SEQ * DH;

    for (int t = 0; t < ntiles; t++) {
        // cooperatively load 64x64 K and V tiles (4096 floats each)
        const float4* Ks = (const float4*)(Kb + (size_t)t * 64 * DH);
        const float4* Vs = (const float4*)(Vb + (size_t)t * 64 * DH);
        float4* Kd = (float4*)&Ksh[0][0];
        float4* Vd = (float4*)&Vsh[0][0];
        #pragma unroll
        for (int i = 0; i < 8; i++) {
            int idx = threadIdx.x + i * 128;
            Kd[idx] = Ks[idx];
            Vd[idx] = Vs[idx];
        }
        __syncthreads();

        int jmax = row - t * 64 + 1;
        if (jmax > 64) jmax = 64;
        for (int j = 0; j < jmax; j++) {
            float s0 = 0.f, s1 = 0.f, s2 = 0.f, s3 = 0.f;
            #pragma unroll
            for (int d = 0; d < DH; d += 4) {
                s0 += q[d+0] * Ksh[j][d+0];
                s1 += q[d+1] * Ksh[j][d+1];
                s2 += q[d+2] * Ksh[j][d+2];
                s3 += q[d+3] * Ksh[j][d+3];
            }
            float s = ((s0 + s1) + (s2 + s3)) * 0.125f;  // 1/sqrt(64)

            if (s > m) {
                float c = __expf(m - s);
                l *= c;
                #pragma unroll
                for (int d = 0; d < DH; d++) o[d] *= c;
                m = s;
            }
            float p = __expf(s - m);
            l += p;
            #pragma unroll
            for (int d = 0; d < DH; d++) o[d] += p * Vsh[j][d];
        }
        __syncthreads();
    }

    const int b = bh >> 4, h = bh & 15;
    const float inv = 1.f / l;
    float* dst = O + ((size_t)(b * SEQ + row)) * DM + h * DH;
    #pragma unroll
    for (int d = 0; d < DH; d += 4) {
        float4 v = make_float4(o[d]*inv, o[d+1]*inv, o[d+2]*inv, o[d+3]*inv);
        *(float4*)(dst + d) = v;
    }
}

// ---------------- launcher ----------------
extern "C" void kernel_launch(void* const* d_in, const int* in_sizes, int n_in,
                              void* d_out, int out_size)
{
    const float* x  = (const float*)d_in[0];
    const float* Wq = (const float*)d_in[1];
    const float* bq = (const float*)d_in[2];
    const float* Wk = (const float*)d_in[3];
    const float* bk = (const float*)d_in[4];
    const float* Wv = (const float*)d_in[5];
    const float* bv = (const float*)d_in[6];
    const float* Wo = (const float*)d_in[7];
    const float* bo = (const float*)d_in[8];
    float* out = (float*)d_out;

    float *qp, *kp, *vp, *ap;
    cudaGetSymbolAddress((void**)&qp, g_Q);
    cudaGetSymbolAddress((void**)&kp, g_K);
    cudaGetSymbolAddress((void**)&vp, g_V);
    cudaGetSymbolAddress((void**)&ap, g_A);

    dim3 gg(DM / BN, MROWS / BM);   // (16, 64)
    gemm_bias_kernel<<<gg, 256>>>(x, Wq, bq, qp, MROWS, DM, DM, 1);
    gemm_bias_kernel<<<gg, 256>>>(x, Wk, bk, kp, MROWS, DM, DM, 1);
    gemm_bias_kernel<<<gg, 256>>>(x, Wv, bv, vp, MROWS, DM, DM, 2);

    attn_kernel<<<dim3(SEQ / 128, BATCH * NH), 128>>>(qp, kp, vp, ap);

    gemm_bias_kernel<<<gg, 256>>>(ap, Wo, bo, out, MROWS, DM, DM, 0);
}

// round 7
// speedup vs baseline: 1.4949x; 1.4949x over previous
#include <cuda_runtime.h>
#include <cstdint>
#include <math.h>

// ---------------- problem constants ----------------
#define BATCH 2
#define SEQ   2048
#define DM    1024
#define NH    16
#define DH    64
#define MROWS (BATCH*SEQ)   // 4096

// ---------------- scratch ----------------
__device__ float g_Q[(size_t)BATCH*NH*SEQ*DH];
__device__ float g_K[(size_t)BATCH*NH*SEQ*DH];
__device__ float g_V[(size_t)BATCH*NH*SEQ*DH];
__device__ float g_A[(size_t)BATCH*SEQ*DM];

// round-to-nearest-even fp32 -> tf32
__device__ __forceinline__ float tf32r(float x) {
    uint32_t u = __float_as_uint(x);
    uint32_t r = (u + 0xFFFu + ((u >> 13) & 1u)) & 0xFFFFE000u;
    return __uint_as_float(r);
}

__device__ __forceinline__ void mma_tf32(float* d, const uint32_t* a, const uint32_t* b) {
    asm volatile(
        "mma.sync.aligned.m16n8k8.row.col.f32.tf32.tf32.f32 "
        "{%0,%1,%2,%3}, {%4,%5,%6,%7}, {%8,%9}, {%0,%1,%2,%3};"
        : "+f"(d[0]), "+f"(d[1]), "+f"(d[2]), "+f"(d[3])
        : "r"(a[0]), "r"(a[1]), "r"(a[2]), "r"(a[3]), "r"(b[0]), "r"(b[1]));
}

// ---------------- HMMA tf32 GEMM: C = A(MxK) * W(NxK)^T + bias ----------------
// CTA tile 128x128, K-chunk 32, double-buffered smem in FRAGMENT-ORDER layout.
// 8 warps = 4(m) x 2(n); warp tile 32x64 = 2 mtiles x 8 ntiles of m16n8.
// mode 0: row-major C[m*DM+n]; mode 1: rotate_half -> [b][h][t][dh]; mode 2: plain -> [b][h][t][dh]
#define GM 128
#define GN 128
#define GKC 32
#define NCHUNK (DM/GKC)        // 32

// smem (floats): bias[128] | A0[4096] | B0[4096] | A1[4096] | B1[4096]
#define SM_BIAS 0
#define SM_A0   128
#define SM_B0   (SM_A0 + 4096)
#define SM_A1   (SM_B0 + 4096)
#define SM_B1   (SM_A1 + 4096)
#define GSMEM_FLOATS (SM_B1 + 4096)
#define GSMEM_BYTES  (GSMEM_FLOATS * 4)   // 66048

__global__ __launch_bounds__(256)
void gemm_mma_kernel(const float* __restrict__ A, const float* __restrict__ W,
                     const float* __restrict__ bias, float* __restrict__ C, int mode)
{
    extern __shared__ float sm[];
    const int tid  = threadIdx.x;
    const int lane = tid & 31;
    const int wid  = tid >> 5;
    const int wm   = wid & 3;      // m-warp 0..3 (32 rows each)
    const int wn   = wid >> 2;     // n-warp 0..1 (64 cols each)
    const int m0   = blockIdx.y * GM;
    const int n0   = blockIdx.x * GN;

    if (tid < 128) sm[SM_BIAS + tid] = bias[n0 + tid];

    // loader-invariant decomposition: idx = i*256 + tid; row = idx>>3, q = idx&7
    int l_row[4], l_q[4];
    #pragma unroll
    for (int i = 0; i < 4; i++) { int idx = i * 256 + tid; l_row[i] = idx >> 3; l_q[i] = idx & 7; }

    // ---- stage chunk 0 ----
    float4 ra[4], rw[4];
    {
        const float* Ac = A + (size_t)m0 * DM;
        const float* Wc = W + (size_t)n0 * DM;
        #pragma unroll
        for (int i = 0; i < 4; i++) {
            ra[i] = *(const float4*)(Ac + (size_t)l_row[i] * DM + l_q[i] * 4);
            rw[i] = *(const float4*)(Wc + (size_t)l_row[i] * DM + l_q[i] * 4);
        }
    }
    #pragma unroll
    for (int i = 0; i < 4; i++) {
        const int row = l_row[i], q = l_q[i];
        const int ks = q >> 1, rh = q & 1;
        // A: [(mt*4+ks)*128 + lane*4 + areg], lane = ((r&7)<<2)|j, areg = (r>>3)&1 | rh<<1
        {
            const int mt = row >> 4, r = row & 15;
            float* ab = sm + SM_A0 + (mt * 4 + ks) * 128 + ((r >> 3) & 1) + (rh << 1);
            const float v[4] = {ra[i].x, ra[i].y, ra[i].z, ra[i].w};
            #pragma unroll
            for (int j = 0; j < 4; j++) ab[(((r & 7) << 2) | j) * 4] = tf32r(v[j]);
        }
        // B: [(nt*4+ks)*64 + lane*2 + breg], lane = ((n&7)<<2)|j, breg = rh
        {
            const int nt = row >> 3, g = row & 7;
            float* bb = sm + SM_B0 + (nt * 4 + ks) * 64 + rh;
            const float v[4] = {rw[i].x, rw[i].y, rw[i].z, rw[i].w};
            #pragma unroll
            for (int j = 0; j < 4; j++) bb[(((g) << 2) | j) * 2] = tf32r(v[j]);
        }
    }
    __syncthreads();

    float acc[2][8][4];
    #pragma unroll
    for (int mt = 0; mt < 2; mt++)
        #pragma unroll
        for (int nt = 0; nt < 8; nt++)
            #pragma unroll
            for (int e = 0; e < 4; e++) acc[mt][nt][e] = 0.f;

    for (int c = 0; c < NCHUNK; c++) {
        const int p = c & 1;
        const float* Ab = sm + (p ? SM_A1 : SM_A0);
        const float* Bb = sm + (p ? SM_B1 : SM_B0);

        // prefetch next chunk into regs (overlaps with compute below)
        if (c + 1 < NCHUNK) {
            const float* Ac = A + (size_t)m0 * DM + (c + 1) * GKC;
            const float* Wc = W + (size_t)n0 * DM + (c + 1) * GKC;
            #pragma unroll
            for (int i = 0; i < 4; i++) {
                ra[i] = *(const float4*)(Ac + (size_t)l_row[i] * DM + l_q[i] * 4);
                rw[i] = *(const float4*)(Wc + (size_t)l_row[i] * DM + l_q[i] * 4);
            }
        }

        // compute: 4 k-steps of 8
        #pragma unroll
        for (int ks = 0; ks < 4; ks++) {
            uint32_t afr[2][4];
            #pragma unroll
            for (int mt = 0; mt < 2; mt++) {
                const int mtg = wm * 2 + mt;
                float4 av = *(const float4*)(Ab + (mtg * 4 + ks) * 128 + lane * 4);
                afr[mt][0] = __float_as_uint(av.x); afr[mt][1] = __float_as_uint(av.y);
                afr[mt][2] = __float_as_uint(av.z); afr[mt][3] = __float_as_uint(av.w);
            }
            uint32_t bfr[8][2];
            #pragma unroll
            for (int nt = 0; nt < 8; nt++) {
                const int ntg = wn * 8 + nt;
                float2 bv = *(const float2*)(Bb + (ntg * 4 + ks) * 64 + lane * 2);
                bfr[nt][0] = __float_as_uint(bv.x); bfr[nt][1] = __float_as_uint(bv.y);
            }
            #pragma unroll
            for (int mt = 0; mt < 2; mt++)
                #pragma unroll
                for (int nt = 0; nt < 8; nt++)
                    mma_tf32(acc[mt][nt], afr[mt], bfr[nt]);
        }

        // store staged regs into the other buffer
        if (c + 1 < NCHUNK) {
            float* An = sm + (p ? SM_A0 : SM_A1);
            float* Bn = sm + (p ? SM_B0 : SM_B1);
            #pragma unroll
            for (int i = 0; i < 4; i++) {
                const int row = l_row[i], q = l_q[i];
                const int ks = q >> 1, rh = q & 1;
                {
                    const int mt = row >> 4, r = row & 15;
                    float* ab = An + (mt * 4 + ks) * 128 + ((r >> 3) & 1) + (rh << 1);
                    const float v[4] = {ra[i].x, ra[i].y, ra[i].z, ra[i].w};
                    #pragma unroll
                    for (int j = 0; j < 4; j++) ab[(((r & 7) << 2) | j) * 4] = tf32r(v[j]);
                }
                {
                    const int nt = row >> 3, g = row & 7;
                    float* bb = Bn + (nt * 4 + ks) * 64 + rh;
                    const float v[4] = {rw[i].x, rw[i].y, rw[i].z, rw[i].w};
                    #pragma unroll
                    for (int j = 0; j < 4; j++) bb[(((g) << 2) | j) * 2] = tf32r(v[j]);
                }
            }
        }
        __syncthreads();
    }

    // ---- epilogue ----
    const int g = lane >> 2, t = lane & 3;
    const float* bs = sm + SM_BIAS;

    #pragma unroll
    for (int mt = 0; mt < 2; mt++) {
        #pragma unroll
        for (int nt = 0; nt < 8; nt++) {
            const int colL = wn * 64 + nt * 8 + t * 2;     // col within tile (even)
            const int col  = n0 + colL;
            #pragma unroll
            for (int half = 0; half < 2; half++) {
                const int m = m0 + wm * 32 + mt * 16 + g + half * 8;
                float y0 = acc[mt][nt][half * 2 + 0] + bs[colL];
                float y1 = acc[mt][nt][half * 2 + 1] + bs[colL + 1];
                if (mode == 0) {
                    *(float2*)(C + (size_t)m * DM + col) = make_float2(y0, y1);
                } else {
                    const int b  = m >> 11;
                    const int ts = m & 2047;
                    const int h  = col >> 6;
                    const int dh = col & 63;
                    float2 o = (mode == 1) ? make_float2(-y1, y0) : make_float2(y0, y1);
                    *(float2*)(C + (((size_t)(b * NH + h) * SEQ) + ts) * DH + dh) = o;
                }
            }
        }
    }
}

// ---------------- attention: causal flash, 1 query row per thread (fp32) ----------------
__global__ __launch_bounds__(128)
void attn_kernel(const float* __restrict__ Q, const float* __restrict__ K,
                 const float* __restrict__ V, float* __restrict__ O)
{
    __shared__ float Ksh[64][64];
    __shared__ float Vsh[64][64];

    const int bh  = blockIdx.y;
    const int row = blockIdx.x * 128 + threadIdx.x;

    const float* Qrow = Q + ((size_t)bh * SEQ + row) * DH;
    float q[DH], o[DH];
    #pragma unroll
    for (int d = 0; d < DH; d++) { q[d] = Qrow[d]; o[d] = 0.f; }

    float m = -INFINITY, l = 0.f;
    const int ntiles = 2 * blockIdx.x + 2;

    const float* Kb = K + (size_t)bh * SEQ * DH;
    const float* Vb = V + (size_t)bh * SEQ * DH;

    for (int t = 0; t < ntiles; t++) {
        const float4* Ks = (const float4*)(Kb + (size_t)t * 64 * DH);
        const float4* Vs = (const float4*)(Vb + (size_t)t * 64 * DH);
        float4* Kd = (float4*)&Ksh[0][0];
        float4* Vd = (float4*)&Vsh[0][0];
        #pragma unroll
        for (int i = 0; i < 8; i++) {
            int idx = threadIdx.x + i * 128;
            Kd[idx] = Ks[idx];
            Vd[idx] = Vs[idx];
        }
        __syncthreads();

        int jmax = row - t * 64 + 1;
        if (jmax > 64) jmax = 64;
        for (int j = 0; j < jmax; j++) {
            float s0 = 0.f, s1 = 0.f, s2 = 0.f, s3 = 0.f;
            #pragma unroll
            for (int d = 0; d < DH; d += 4) {
                s0 += q[d+0] * Ksh[j][d+0];
                s1 += q[d+1] * Ksh[j][d+1];
                s2 += q[d+2] * Ksh[j][d+2];
                s3 += q[d+3] * Ksh[j][d+3];
            }
            float s = ((s0 + s1) + (s2 + s3)) * 0.125f;

            if (s > m) {
                float c = __expf(m - s);
                l *= c;
                #pragma unroll
                for (int d = 0; d < DH; d++) o[d] *= c;
                m = s;
            }
            float p = __expf(s - m);
            l += p;
            #pragma unroll
            for (int d = 0; d < DH; d++) o[d] += p * Vsh[j][d];
        }
        __syncthreads();
    }

    const int b = bh >> 4, h = bh & 15;
    const float inv = 1.f / l;
    float* dst = O + ((size_t)(b * SEQ + row)) * DM + h * DH;
    #pragma unroll
    for (int d = 0; d < DH; d += 4) {
        float4 v = make_float4(o[d]*inv, o[d+1]*inv, o[d+2]*inv, o[d+3]*inv);
        *(float4*)(dst + d) = v;
    }
}

// ---------------- launcher ----------------
extern "C" void kernel_launch(void* const* d_in, const int* in_sizes, int n_in,
                              void* d_out, int out_size)
{
    const float* x  = (const float*)d_in[0];
    const float* Wq = (const float*)d_in[1];
    const float* bq = (const float*)d_in[2];
    const float* Wk = (const float*)d_in[3];
    const float* bk = (const float*)d_in[4];
    const float* Wv = (const float*)d_in[5];
    const float* bv = (const float*)d_in[6];
    const float* Wo = (const float*)d_in[7];
    const float* bo = (const float*)d_in[8];
    float* out = (float*)d_out;

    float *qp, *kp, *vp, *ap;
    cudaGetSymbolAddress((void**)&qp, g_Q);
    cudaGetSymbolAddress((void**)&kp, g_K);
    cudaGetSymbolAddress((void**)&vp, g_V);
    cudaGetSymbolAddress((void**)&ap, g_A);

    cudaFuncSetAttribute(gemm_mma_kernel, cudaFuncAttributeMaxDynamicSharedMemorySize, GSMEM_BYTES);

    dim3 gg(DM / GN, MROWS / GM);   // (8, 32)
    gemm_mma_kernel<<<gg, 256, GSMEM_BYTES>>>(x, Wq, bq, qp, 1);
    gemm_mma_kernel<<<gg, 256, GSMEM_BYTES>>>(x, Wk, bk, kp, 1);
    gemm_mma_kernel<<<gg, 256, GSMEM_BYTES>>>(x, Wv, bv, vp, 2);

    attn_kernel<<<dim3(SEQ / 128, BATCH * NH), 128>>>(qp, kp, vp, ap);

    gemm_mma_kernel<<<gg, 256, GSMEM_BYTES>>>(ap, Wo, bo, out, 0);
}

// round 8
// speedup vs baseline: 2.7188x; 1.8187x over previous
#include <cuda_runtime.h>
#include <cstdint>
#include <math.h>

// ---------------- problem constants ----------------
#define BATCH 2
#define SEQ   2048
#define DM    1024
#define NH    16
#define DH    64
#define MROWS (BATCH*SEQ)   // 4096

// ---------------- scratch ----------------
__device__ float g_Q[(size_t)BATCH*NH*SEQ*DH];
__device__ float g_K[(size_t)BATCH*NH*SEQ*DH];
__device__ float g_V[(size_t)BATCH*NH*SEQ*DH];
__device__ float g_A[(size_t)BATCH*SEQ*DM];

// round-to-nearest fp32 -> tf32
__device__ __forceinline__ float tf32r(float x) {
    uint32_t u = __float_as_uint(x);
    uint32_t r = (u + 0xFFFu + ((u >> 13) & 1u)) & 0xFFFFE000u;
    return __uint_as_float(r);
}
__device__ __forceinline__ uint32_t cvt_tf32(float x) {
    uint32_t r;
    asm("cvt.rna.tf32.f32 %0, %1;" : "=r"(r) : "f"(x));
    return r;
}

__device__ __forceinline__ void mma_tf32(float* d, const uint32_t* a, uint32_t b0, uint32_t b1) {
    asm volatile(
        "mma.sync.aligned.m16n8k8.row.col.f32.tf32.tf32.f32 "
        "{%0,%1,%2,%3}, {%4,%5,%6,%7}, {%8,%9}, {%0,%1,%2,%3};"
        : "+f"(d[0]), "+f"(d[1]), "+f"(d[2]), "+f"(d[3])
        : "r"(a[0]), "r"(a[1]), "r"(a[2]), "r"(a[3]), "r"(b0), "r"(b1));
}

// ---------------- HMMA tf32 GEMM (unchanged from R7) ----------------
#define GM 128
#define GN 128
#define GKC 32
#define NCHUNK (DM/GKC)

#define SM_BIAS 0
#define SM_A0   128
#define SM_B0   (SM_A0 + 4096)
#define SM_A1   (SM_B0 + 4096)
#define SM_B1   (SM_A1 + 4096)
#define GSMEM_FLOATS (SM_B1 + 4096)
#define GSMEM_BYTES  (GSMEM_FLOATS * 4)

__global__ __launch_bounds__(256)
void gemm_mma_kernel(const float* __restrict__ A, const float* __restrict__ W,
                     const float* __restrict__ bias, float* __restrict__ C, int mode)
{
    extern __shared__ float sm[];
    const int tid  = threadIdx.x;
    const int lane = tid & 31;
    const int wid  = tid >> 5;
    const int wm   = wid & 3;
    const int wn   = wid >> 2;
    const int m0   = blockIdx.y * GM;
    const int n0   = blockIdx.x * GN;

    if (tid < 128) sm[SM_BIAS + tid] = bias[n0 + tid];

    int l_row[4], l_q[4];
    #pragma unroll
    for (int i = 0; i < 4; i++) { int idx = i * 256 + tid; l_row[i] = idx >> 3; l_q[i] = idx & 7; }

    float4 ra[4], rw[4];
    {
        const float* Ac = A + (size_t)m0 * DM;
        const float* Wc = W + (size_t)n0 * DM;
        #pragma unroll
        for (int i = 0; i < 4; i++) {
            ra[i] = *(const float4*)(Ac + (size_t)l_row[i] * DM + l_q[i] * 4);
            rw[i] = *(const float4*)(Wc + (size_t)l_row[i] * DM + l_q[i] * 4);
        }
    }
    #pragma unroll
    for (int i = 0; i < 4; i++) {
        const int row = l_row[i], q = l_q[i];
        const int ks = q >> 1, rh = q & 1;
        {
            const int mt = row >> 4, r = row & 15;
            float* ab = sm + SM_A0 + (mt * 4 + ks) * 128 + ((r >> 3) & 1) + (rh << 1);
            const float v[4] = {ra[i].x, ra[i].y, ra[i].z, ra[i].w};
            #pragma unroll
            for (int j = 0; j < 4; j++) ab[(((r & 7) << 2) | j) * 4] = tf32r(v[j]);
        }
        {
            const int nt = row >> 3, g = row & 7;
            float* bb = sm + SM_B0 + (nt * 4 + ks) * 64 + rh;
            const float v[4] = {rw[i].x, rw[i].y, rw[i].z, rw[i].w};
            #pragma unroll
            for (int j = 0; j < 4; j++) bb[(((g) << 2) | j) * 2] = tf32r(v[j]);
        }
    }
    __syncthreads();

    float acc[2][8][4];
    #pragma unroll
    for (int mt = 0; mt < 2; mt++)
        #pragma unroll
        for (int nt = 0; nt < 8; nt++)
            #pragma unroll
            for (int e = 0; e < 4; e++) acc[mt][nt][e] = 0.f;

    for (int c = 0; c < NCHUNK; c++) {
        const int p = c & 1;
        const float* Ab = sm + (p ? SM_A1 : SM_A0);
        const float* Bb = sm + (p ? SM_B1 : SM_B0);

        if (c + 1 < NCHUNK) {
            const float* Ac = A + (size_t)m0 * DM + (c + 1) * GKC;
            const float* Wc = W + (size_t)n0 * DM + (c + 1) * GKC;
            #pragma unroll
            for (int i = 0; i < 4; i++) {
                ra[i] = *(const float4*)(Ac + (size_t)l_row[i] * DM + l_q[i] * 4);
                rw[i] = *(const float4*)(Wc + (size_t)l_row[i] * DM + l_q[i] * 4);
            }
        }

        #pragma unroll
        for (int ks = 0; ks < 4; ks++) {
            uint32_t afr[2][4];
            #pragma unroll
            for (int mt = 0; mt < 2; mt++) {
                const int mtg = wm * 2 + mt;
                float4 av = *(const float4*)(Ab + (mtg * 4 + ks) * 128 + lane * 4);
                afr[mt][0] = __float_as_uint(av.x); afr[mt][1] = __float_as_uint(av.y);
                afr[mt][2] = __float_as_uint(av.z); afr[mt][3] = __float_as_uint(av.w);
            }
            uint32_t bfr[8][2];
            #pragma unroll
            for (int nt = 0; nt < 8; nt++) {
                const int ntg = wn * 8 + nt;
                float2 bv = *(const float2*)(Bb + (ntg * 4 + ks) * 64 + lane * 2);
                bfr[nt][0] = __float_as_uint(bv.x); bfr[nt][1] = __float_as_uint(bv.y);
            }
            #pragma unroll
            for (int mt = 0; mt < 2; mt++)
                #pragma unroll
                for (int nt = 0; nt < 8; nt++)
                    mma_tf32(acc[mt][nt], afr[mt], bfr[nt][0], bfr[nt][1]);
        }

        if (c + 1 < NCHUNK) {
            float* An = sm + (p ? SM_A0 : SM_A1);
            float* Bn = sm + (p ? SM_B0 : SM_B1);
            #pragma unroll
            for (int i = 0; i < 4; i++) {
                const int row = l_row[i], q = l_q[i];
                const int ks = q >> 1, rh = q & 1;
                {
                    const int mt = row >> 4, r = row & 15;
                    float* ab = An + (mt * 4 + ks) * 128 + ((r >> 3) & 1) + (rh << 1);
                    const float v[4] = {ra[i].x, ra[i].y, ra[i].z, ra[i].w};
                    #pragma unroll
                    for (int j = 0; j < 4; j++) ab[(((r & 7) << 2) | j) * 4] = tf32r(v[j]);
                }
                {
                    const int nt = row >> 3, g = row & 7;
                    float* bb = Bn + (nt * 4 + ks) * 64 + rh;
                    const float v[4] = {rw[i].x, rw[i].y, rw[i].z, rw[i].w};
                    #pragma unroll
                    for (int j = 0; j < 4; j++) bb[(((g) << 2) | j) * 2] = tf32r(v[j]);
                }
            }
        }
        __syncthreads();
    }

    const int g = lane >> 2, t = lane & 3;
    const float* bs = sm + SM_BIAS;

    #pragma unroll
    for (int mt = 0; mt < 2; mt++) {
        #pragma unroll
        for (int nt = 0; nt < 8; nt++) {
            const int colL = wn * 64 + nt * 8 + t * 2;
            const int col  = n0 + colL;
            #pragma unroll
            for (int half = 0; half < 2; half++) {
                const int m = m0 + wm * 32 + mt * 16 + g + half * 8;
                float y0 = acc[mt][nt][half * 2 + 0] + bs[colL];
                float y1 = acc[mt][nt][half * 2 + 1] + bs[colL + 1];
                if (mode == 0) {
                    *(float2*)(C + (size_t)m * DM + col) = make_float2(y0, y1);
                } else {
                    const int b  = m >> 11;
                    const int ts = m & 2047;
                    const int h  = col >> 6;
                    const int dh = col & 63;
                    float2 o = (mode == 1) ? make_float2(-y1, y0) : make_float2(y0, y1);
                    *(float2*)(C + (((size_t)(b * NH + h) * SEQ) + ts) * DH + dh) = o;
                }
            }
        }
    }
}

// ---------------- HMMA tf32 flash attention ----------------
// CTA: 128 q-rows, 4 warps x 32 rows (2 mtiles of 16). KV tiles of 64 keys.
// smem: Qs[128][68] | Kt[64][72] (d-major) | Vt[64][68] (d-major)
#define AQ_LD 68
#define AK_LD 72
#define AV_LD 68
#define A_OFF_Q 0
#define A_OFF_K (128*AQ_LD)                 // 8704
#define A_OFF_V (A_OFF_K + 64*AK_LD)        // 13312
#define A_SMEM_FLOATS (A_OFF_V + 64*AV_LD)  // 17664
#define A_SMEM_BYTES (A_SMEM_FLOATS*4)      // 70656

__global__ __launch_bounds__(128)
void attn_mma_kernel(const float* __restrict__ Q, const float* __restrict__ K,
                     const float* __restrict__ V, float* __restrict__ O)
{
    extern __shared__ float sm[];
    float* Qs = sm + A_OFF_Q;
    float* Kt = sm + A_OFF_K;
    float* Vt = sm + A_OFF_V;

    const int tid  = threadIdx.x;
    const int lane = tid & 31;
    const int w    = tid >> 5;        // 0..3
    const int g    = lane >> 2;       // 0..7
    const int t    = lane & 3;        // 0..3
    const int bh   = blockIdx.y;      // 0..31
    const int qb   = (gridDim.x - 1) - blockIdx.x;   // heavy blocks first
    const int qblk = qb * 128;

    const float* Qg = Q + (size_t)bh * SEQ * DH;
    const float* Kg = K + (size_t)bh * SEQ * DH;
    const float* Vg = V + (size_t)bh * SEQ * DH;

    // ---- stage Q (one row per thread), scale 1/sqrt(64), tf32-round ----
    {
        const float* src = Qg + (size_t)(qblk + tid) * DH;
        float* dst = Qs + tid * AQ_LD;
        #pragma unroll
        for (int j = 0; j < 16; j++) {
            float4 v = *(const float4*)(src + j * 4);
            dst[j*4+0] = tf32r(v.x * 0.125f);
            dst[j*4+1] = tf32r(v.y * 0.125f);
            dst[j*4+2] = tf32r(v.z * 0.125f);
            dst[j*4+3] = tf32r(v.w * 0.125f);
        }
    }

    float o[2][8][4];
    #pragma unroll
    for (int mt = 0; mt < 2; mt++)
        #pragma unroll
        for (int nt = 0; nt < 8; nt++)
            #pragma unroll
            for (int e = 0; e < 4; e++) o[mt][nt][e] = 0.f;
    float mrow[2][2] = {{-1e30f, -1e30f}, {-1e30f, -1e30f}};
    float lrow[2][2] = {{0.f, 0.f}, {0.f, 0.f}};

    const int ntiles = 2 * qb + 2;
    const int wrow   = qblk + w * 32;
    const int wmax   = wrow + 31;

    const int skey = tid & 63;
    const int sd0  = (tid >> 6) * 32;

    for (int kt = 0; kt < ntiles; kt++) {
        const int kbase = kt * 64;
        __syncthreads();
        // ---- stage K^T[d][key] (ld 72), V^T[d][key] (ld 68) ----
        {
            const float* kp = Kg + (size_t)(kbase + skey) * DH + sd0;
            const float* vp = Vg + (size_t)(kbase + skey) * DH + sd0;
            #pragma unroll
            for (int i = 0; i < 8; i++) {
                float4 kv = *(const float4*)(kp + i * 4);
                Kt[(sd0 + i*4 + 0) * AK_LD + skey] = tf32r(kv.x);
                Kt[(sd0 + i*4 + 1) * AK_LD + skey] = tf32r(kv.y);
                Kt[(sd0 + i*4 + 2) * AK_LD + skey] = tf32r(kv.z);
                Kt[(sd0 + i*4 + 3) * AK_LD + skey] = tf32r(kv.w);
                float4 vv = *(const float4*)(vp + i * 4);
                Vt[(sd0 + i*4 + 0) * AV_LD + skey] = tf32r(vv.x);
                Vt[(sd0 + i*4 + 1) * AV_LD + skey] = tf32r(vv.y);
                Vt[(sd0 + i*4 + 2) * AV_LD + skey] = tf32r(vv.z);
                Vt[(sd0 + i*4 + 3) * AV_LD + skey] = tf32r(vv.w);
            }
        }
        __syncthreads();
        if (kbase > wmax) continue;   // warp entirely above diagonal

        // ---- S = Q K^T : s[mt][nt][4], 16x8 tiles ----
        float s[2][8][4];
        #pragma unroll
        for (int mt = 0; mt < 2; mt++)
            #pragma unroll
            for (int nt = 0; nt < 8; nt++)
                #pragma unroll
                for (int e = 0; e < 4; e++) s[mt][nt][e] = 0.f;

        #pragma unroll
        for (int ks = 0; ks < 8; ks++) {
            uint32_t af[2][4];
            #pragma unroll
            for (int mt = 0; mt < 2; mt++) {
                const int r0 = w * 32 + mt * 16 + g;
                af[mt][0] = __float_as_uint(Qs[(r0    ) * AQ_LD + ks*8 + t    ]);
                af[mt][1] = __float_as_uint(Qs[(r0 + 8) * AQ_LD + ks*8 + t    ]);
                af[mt][2] = __float_as_uint(Qs[(r0    ) * AQ_LD + ks*8 + t + 4]);
                af[mt][3] = __float_as_uint(Qs[(r0 + 8) * AQ_LD + ks*8 + t + 4]);
            }
            #pragma unroll
            for (int nt = 0; nt < 8; nt++) {
                uint32_t b0 = __float_as_uint(Kt[(ks*8 + t    ) * AK_LD + nt*8 + g]);
                uint32_t b1 = __float_as_uint(Kt[(ks*8 + t + 4) * AK_LD + nt*8 + g]);
                mma_tf32(s[0][nt], af[0], b0, b1);
                mma_tf32(s[1][nt], af[1], b0, b1);
            }
        }

        // ---- causal mask (only diagonal tiles) ----
        if (kbase + 63 > wrow) {
            #pragma unroll
            for (int mt = 0; mt < 2; mt++) {
                const int r0 = wrow + mt * 16 + g;
                const int r1 = r0 + 8;
                #pragma unroll
                for (int nt = 0; nt < 8; nt++) {
                    const int key = kbase + nt * 8 + 2 * t;
                    if (key     > r0) s[mt][nt][0] = -1e30f;
                    if (key + 1 > r0) s[mt][nt][1] = -1e30f;
                    if (key     > r1) s[mt][nt][2] = -1e30f;
                    if (key + 1 > r1) s[mt][nt][3] = -1e30f;
                }
            }
        }

        // ---- online softmax ----
        #pragma unroll
        for (int mt = 0; mt < 2; mt++) {
            float mx0 = -1e30f, mx1 = -1e30f;
            #pragma unroll
            for (int nt = 0; nt < 8; nt++) {
                mx0 = fmaxf(mx0, fmaxf(s[mt][nt][0], s[mt][nt][1]));
                mx1 = fmaxf(mx1, fmaxf(s[mt][nt][2], s[mt][nt][3]));
            }
            mx0 = fmaxf(mx0, __shfl_xor_sync(0xFFFFFFFFu, mx0, 1));
            mx0 = fmaxf(mx0, __shfl_xor_sync(0xFFFFFFFFu, mx0, 2));
            mx1 = fmaxf(mx1, __shfl_xor_sync(0xFFFFFFFFu, mx1, 1));
            mx1 = fmaxf(mx1, __shfl_xor_sync(0xFFFFFFFFu, mx1, 2));
            const float mn0 = fmaxf(mrow[mt][0], mx0);
            const float mn1 = fmaxf(mrow[mt][1], mx1);
            const float c0 = __expf(mrow[mt][0] - mn0);
            const float c1 = __expf(mrow[mt][1] - mn1);
            lrow[mt][0] *= c0; lrow[mt][1] *= c1;
            #pragma unroll
            for (int nt = 0; nt < 8; nt++) {
                o[mt][nt][0] *= c0; o[mt][nt][1] *= c0;
                o[mt][nt][2] *= c1; o[mt][nt][3] *= c1;
            }
            mrow[mt][0] = mn0; mrow[mt][1] = mn1;
            float rs0 = 0.f, rs1 = 0.f;
            #pragma unroll
            for (int nt = 0; nt < 8; nt++) {
                s[mt][nt][0] = __expf(s[mt][nt][0] - mn0);
                s[mt][nt][1] = __expf(s[mt][nt][1] - mn0);
                s[mt][nt][2] = __expf(s[mt][nt][2] - mn1);
                s[mt][nt][3] = __expf(s[mt][nt][3] - mn1);
                rs0 += s[mt][nt][0] + s[mt][nt][1];
                rs1 += s[mt][nt][2] + s[mt][nt][3];
            }
            rs0 += __shfl_xor_sync(0xFFFFFFFFu, rs0, 1);
            rs0 += __shfl_xor_sync(0xFFFFFFFFu, rs0, 2);
            rs1 += __shfl_xor_sync(0xFFFFFFFFu, rs1, 1);
            rs1 += __shfl_xor_sync(0xFFFFFFFFu, rs1, 2);
            lrow[mt][0] += rs0; lrow[mt][1] += rs1;
        }

        // ---- O += P V : transpose P frags via shfl, mma against V^T ----
        const int src1 = (g << 2) | (t >> 1);
        const int src2 = src1 + 2;
        const bool odd = (t & 1) != 0;
        #pragma unroll
        for (int ks = 0; ks < 8; ks++) {
            uint32_t af[2][4];
            #pragma unroll
            for (int mt = 0; mt < 2; mt++) {
                float e0 = __shfl_sync(0xFFFFFFFFu, s[mt][ks][0], src1);
                float e1 = __shfl_sync(0xFFFFFFFFu, s[mt][ks][1], src1);
                float e2 = __shfl_sync(0xFFFFFFFFu, s[mt][ks][2], src1);
                float e3 = __shfl_sync(0xFFFFFFFFu, s[mt][ks][3], src1);
                float f0 = __shfl_sync(0xFFFFFFFFu, s[mt][ks][0], src2);
                float f1 = __shfl_sync(0xFFFFFFFFu, s[mt][ks][1], src2);
                float f2 = __shfl_sync(0xFFFFFFFFu, s[mt][ks][2], src2);
                float f3 = __shfl_sync(0xFFFFFFFFu, s[mt][ks][3], src2);
                af[mt][0] = cvt_tf32(odd ? e1 : e0);
                af[mt][1] = cvt_tf32(odd ? e3 : e2);
                af[mt][2] = cvt_tf32(odd ? f1 : f0);
                af[mt][3] = cvt_tf32(odd ? f3 : f2);
            }
            #pragma unroll
            for (int dnt = 0; dnt < 8; dnt++) {
                uint32_t b0 = __float_as_uint(Vt[(dnt*8 + g) * AV_LD + ks*8 + t    ]);
                uint32_t b1 = __float_as_uint(Vt[(dnt*8 + g) * AV_LD + ks*8 + t + 4]);
                mma_tf32(o[0][dnt], af[0], b0, b1);
                mma_tf32(o[1][dnt], af[1], b0, b1);
            }
        }
    }

    // ---- normalize + write [b][t][h*64+dh] ----
    const int b = bh >> 4, h = bh & 15;
    #pragma unroll
    for (int mt = 0; mt < 2; mt++) {
        const float i0 = 1.f / lrow[mt][0];
        const float i1 = 1.f / lrow[mt][1];
        const int r0 = wrow + mt * 16 + g;
        const int r1 = r0 + 8;
        #pragma unroll
        for (int dnt = 0; dnt < 8; dnt++) {
            const int col = h * 64 + dnt * 8 + 2 * t;
            *(float2*)(O + ((size_t)(b * SEQ + r0)) * DM + col) =
                make_float2(o[mt][dnt][0] * i0, o[mt][dnt][1] * i0);
            *(float2*)(O + ((size_t)(b * SEQ + r1)) * DM + col) =
                make_float2(o[mt][dnt][2] * i1, o[mt][dnt][3] * i1);
        }
    }
}

// ---------------- launcher ----------------
extern "C" void kernel_launch(void* const* d_in, const int* in_sizes, int n_in,
                              void* d_out, int out_size)
{
    const float* x  = (const float*)d_in[0];
    const float* Wq = (const float*)d_in[1];
    const float* bq = (const float*)d_in[2];
    const float* Wk = (const float*)d_in[3];
    const float* bk = (const float*)d_in[4];
    const float* Wv = (const float*)d_in[5];
    const float* bv = (const float*)d_in[6];
    const float* Wo = (const float*)d_in[7];
    const float* bo = (const float*)d_in[8];
    float* out = (float*)d_out;

    float *qp, *kp, *vp, *ap;
    cudaGetSymbolAddress((void**)&qp, g_Q);
    cudaGetSymbolAddress((void**)&kp, g_K);
    cudaGetSymbolAddress((void**)&vp, g_V);
    cudaGetSymbolAddress((void**)&ap, g_A);

    cudaFuncSetAttribute(gemm_mma_kernel, cudaFuncAttributeMaxDynamicSharedMemorySize, GSMEM_BYTES);
    cudaFuncSetAttribute(attn_mma_kernel, cudaFuncAttributeMaxDynamicSharedMemorySize, A_SMEM_BYTES);

    dim3 gg(DM / GN, MROWS / GM);   // (8, 32)
    gemm_mma_kernel<<<gg, 256, GSMEM_BYTES>>>(x, Wq, bq, qp, 1);
    gemm_mma_kernel<<<gg, 256, GSMEM_BYTES>>>(x, Wk, bk, kp, 1);
    gemm_mma_kernel<<<gg, 256, GSMEM_BYTES>>>(x, Wv, bv, vp, 2);

    attn_mma_kernel<<<dim3(SEQ / 128, BATCH * NH), 128, A_SMEM_BYTES>>>(qp, kp, vp, ap);

    gemm_mma_kernel<<<gg, 256, GSMEM_BYTES>>>(ap, Wo, bo, out, 0);
}

// round 11
// speedup vs baseline: 3.3446x; 1.2302x over previous
#include <cuda_runtime.h>
#include <cstdint>
#include <math.h>

// ---------------- problem constants ----------------
#define BATCH 2
#define SEQ   2048
#define DM    1024
#define NH    16
#define DH    64
#define MROWS (BATCH*SEQ)   // 4096

// ---------------- scratch ----------------
__device__ float g_Q[(size_t)BATCH*NH*SEQ*DH];
__device__ float g_K[(size_t)BATCH*NH*SEQ*DH];
__device__ float g_V[(size_t)BATCH*NH*SEQ*DH];
__device__ float g_A[(size_t)BATCH*SEQ*DM];

// round-to-nearest fp32 -> tf32
__device__ __forceinline__ float tf32r(float x) {
    uint32_t u = __float_as_uint(x);
    uint32_t r = (u + 0xFFFu + ((u >> 13) & 1u)) & 0xFFFFE000u;
    return __uint_as_float(r);
}
__device__ __forceinline__ uint32_t cvt_tf32(float x) {
    uint32_t r;
    asm("cvt.rna.tf32.f32 %0, %1;" : "=r"(r) : "f"(x));
    return r;
}

__device__ __forceinline__ void mma_tf32(float* d, const uint32_t* a, uint32_t b0, uint32_t b1) {
    asm volatile(
        "mma.sync.aligned.m16n8k8.row.col.f32.tf32.tf32.f32 "
        "{%0,%1,%2,%3}, {%4,%5,%6,%7}, {%8,%9}, {%0,%1,%2,%3};"
        : "+f"(d[0]), "+f"(d[1]), "+f"(d[2]), "+f"(d[3])
        : "r"(a[0]), "r"(a[1]), "r"(a[2]), "r"(a[3]), "r"(b0), "r"(b1));
}

// ---------------- HMMA tf32 GEMM body ----------------
#define GM 128
#define GN 128
#define GKC 32
#define NCHUNK (DM/GKC)

#define SM_BIAS 0
#define SM_A0   128
#define SM_B0   (SM_A0 + 4096)
#define SM_A1   (SM_B0 + 4096)
#define SM_B1   (SM_A1 + 4096)
#define GSMEM_FLOATS (SM_B1 + 4096)
#define GSMEM_BYTES  (GSMEM_FLOATS * 4)

__device__ __forceinline__
void gemm_body(float* sm, const float* __restrict__ A, const float* __restrict__ W,
               const float* __restrict__ bias, float* __restrict__ C, int mode)
{
    const int tid  = threadIdx.x;
    const int lane = tid & 31;
    const int wid  = tid >> 5;
    const int wm   = wid & 3;
    const int wn   = wid >> 2;
    const int m0   = blockIdx.y * GM;
    const int n0   = blockIdx.x * GN;

    if (tid < 128) sm[SM_BIAS + tid] = bias[n0 + tid];

    int l_row[4], l_q[4];
    #pragma unroll
    for (int i = 0; i < 4; i++) { int idx = i * 256 + tid; l_row[i] = idx >> 3; l_q[i] = idx & 7; }

    float4 ra[4], rw[4];
    {
        const float* Ac = A + (size_t)m0 * DM;
        const float* Wc = W + (size_t)n0 * DM;
        #pragma unroll
        for (int i = 0; i < 4; i++) {
            ra[i] = *(const float4*)(Ac + (size_t)l_row[i] * DM + l_q[i] * 4);
            rw[i] = *(const float4*)(Wc + (size_t)l_row[i] * DM + l_q[i] * 4);
        }
    }
    #pragma unroll
    for (int i = 0; i < 4; i++) {
        const int row = l_row[i], q = l_q[i];
        const int ks = q >> 1, rh = q & 1;
        {
            const int mt = row >> 4, r = row & 15;
            float* ab = sm + SM_A0 + (mt * 4 + ks) * 128 + ((r >> 3) & 1) + (rh << 1);
            const float v[4] = {ra[i].x, ra[i].y, ra[i].z, ra[i].w};
            #pragma unroll
            for (int j = 0; j < 4; j++) ab[(((r & 7) << 2) | j) * 4] = tf32r(v[j]);
        }
        {
            const int nt = row >> 3, g = row & 7;
            float* bb = sm + SM_B0 + (nt * 4 + ks) * 64 + rh;
            const float v[4] = {rw[i].x, rw[i].y, rw[i].z, rw[i].w};
            #pragma unroll
            for (int j = 0; j < 4; j++) bb[(((g) << 2) | j) * 2] = tf32r(v[j]);
        }
    }
    __syncthreads();

    float acc[2][8][4];
    #pragma unroll
    for (int mt = 0; mt < 2; mt++)
        #pragma unroll
        for (int nt = 0; nt < 8; nt++)
            #pragma unroll
            for (int e = 0; e < 4; e++) acc[mt][nt][e] = 0.f;

    for (int c = 0; c < NCHUNK; c++) {
        const int p = c & 1;
        const float* Ab = sm + (p ? SM_A1 : SM_A0);
        const float* Bb = sm + (p ? SM_B1 : SM_B0);

        if (c + 1 < NCHUNK) {
            const float* Ac = A + (size_t)m0 * DM + (c + 1) * GKC;
            const float* Wc = W + (size_t)n0 * DM + (c + 1) * GKC;
            #pragma unroll
            for (int i = 0; i < 4; i++) {
                ra[i] = *(const float4*)(Ac + (size_t)l_row[i] * DM + l_q[i] * 4);
                rw[i] = *(const float4*)(Wc + (size_t)l_row[i] * DM + l_q[i] * 4);
            }
        }

        #pragma unroll
        for (int ks = 0; ks < 4; ks++) {
            uint32_t afr[2][4];
            #pragma unroll
            for (int mt = 0; mt < 2; mt++) {
                const int mtg = wm * 2 + mt;
                float4 av = *(const float4*)(Ab + (mtg * 4 + ks) * 128 + lane * 4);
                afr[mt][0] = __float_as_uint(av.x); afr[mt][1] = __float_as_uint(av.y);
                afr[mt][2] = __float_as_uint(av.z); afr[mt][3] = __float_as_uint(av.w);
            }
            uint32_t bfr[8][2];
            #pragma unroll
            for (int nt = 0; nt < 8; nt++) {
                const int ntg = wn * 8 + nt;
                float2 bv = *(const float2*)(Bb + (ntg * 4 + ks) * 64 + lane * 2);
                bfr[nt][0] = __float_as_uint(bv.x); bfr[nt][1] = __float_as_uint(bv.y);
            }
            #pragma unroll
            for (int mt = 0; mt < 2; mt++)
                #pragma unroll
                for (int nt = 0; nt < 8; nt++)
                    mma_tf32(acc[mt][nt], afr[mt], bfr[nt][0], bfr[nt][1]);
        }

        if (c + 1 < NCHUNK) {
            float* An = sm + (p ? SM_A0 : SM_A1);
            float* Bn = sm + (p ? SM_B0 : SM_B1);
            #pragma unroll
            for (int i = 0; i < 4; i++) {
                const int row = l_row[i], q = l_q[i];
                const int ks = q >> 1, rh = q & 1;
                {
                    const int mt = row >> 4, r = row & 15;
                    float* ab = An + (mt * 4 + ks) * 128 + ((r >> 3) & 1) + (rh << 1);
                    const float v[4] = {ra[i].x, ra[i].y, ra[i].z, ra[i].w};
                    #pragma unroll
                    for (int j = 0; j < 4; j++) ab[(((r & 7) << 2) | j) * 4] = tf32r(v[j]);
                }
                {
                    const int nt = row >> 3, g = row & 7;
                    float* bb = Bn + (nt * 4 + ks) * 64 + rh;
                    const float v[4] = {rw[i].x, rw[i].y, rw[i].z, rw[i].w};
                    #pragma unroll
                    for (int j = 0; j < 4; j++) bb[(((g) << 2) | j) * 2] = tf32r(v[j]);
                }
            }
        }
        __syncthreads();
    }

    const int g = lane >> 2, t = lane & 3;
    const float* bs = sm + SM_BIAS;

    #pragma unroll
    for (int mt = 0; mt < 2; mt++) {
        #pragma unroll
        for (int nt = 0; nt < 8; nt++) {
            const int colL = wn * 64 + nt * 8 + t * 2;
            const int col  = n0 + colL;
            #pragma unroll
            for (int half = 0; half < 2; half++) {
                const int m = m0 + wm * 32 + mt * 16 + g + half * 8;
                float y0 = acc[mt][nt][half * 2 + 0] + bs[colL];
                float y1 = acc[mt][nt][half * 2 + 1] + bs[colL + 1];
                if (mode == 0) {
                    *(float2*)(C + (size_t)m * DM + col) = make_float2(y0, y1);
                } else {
                    const int b  = m >> 11;
                    const int ts = m & 2047;
                    const int h  = col >> 6;
                    const int dh = col & 63;
                    float2 o = (mode == 1) ? make_float2(-y1, y0) : make_float2(y0, y1);
                    *(float2*)(C + (((size_t)(b * NH + h) * SEQ) + ts) * DH + dh) = o;
                }
            }
        }
    }
}

// fused QKV: grid.z selects projection
__global__ __launch_bounds__(256)
void gemm_qkv_kernel(const float* __restrict__ x,
                     const float* __restrict__ Wq, const float* __restrict__ bq,
                     const float* __restrict__ Wk, const float* __restrict__ bk,
                     const float* __restrict__ Wv, const float* __restrict__ bv,
                     float* __restrict__ Qo, float* __restrict__ Ko, float* __restrict__ Vo)
{
    extern __shared__ float sm[];
    const int z = blockIdx.z;
    const float* W    = (z == 0) ? Wq : (z == 1) ? Wk : Wv;
    const float* bias = (z == 0) ? bq : (z == 1) ? bk : bv;
    float* C          = (z == 0) ? Qo : (z == 1) ? Ko : Vo;
    gemm_body(sm, x, W, bias, C, (z == 2) ? 2 : 1);
}

__global__ __launch_bounds__(256)
void gemm_o_kernel(const float* __restrict__ A, const float* __restrict__ W,
                   const float* __restrict__ bias, float* __restrict__ C)
{
    extern __shared__ float sm[];
    gemm_body(sm, A, W, bias, C, 0);
}

// ---------------- HMMA tf32 flash attention ----------------
// CTA: 128 q-rows, 4 warps x 32 rows (2 mtiles). KV tiles of 64 keys.
// smem: Qs[128][68] | Ks[64][68] row-major | Vs[64][72] row-major
#define AQ_LD 68
#define AK_LD 68
#define AV_LD 72
#define A_OFF_Q 0
#define A_OFF_K (128*AQ_LD)                 // 8704
#define A_OFF_V (A_OFF_K + 64*AK_LD)        // 13056
#define A_SMEM_FLOATS (A_OFF_V + 64*AV_LD)  // 17664
#define A_SMEM_BYTES (A_SMEM_FLOATS*4)      // 70656

__global__ __launch_bounds__(128, 3)
void attn_mma_kernel(const float* __restrict__ Q, const float* __restrict__ K,
                     const float* __restrict__ V, float* __restrict__ O)
{
    extern __shared__ float sm[];
    float* Qs = sm + A_OFF_Q;
    float* Ks = sm + A_OFF_K;
    float* Vs = sm + A_OFF_V;

    const int tid  = threadIdx.x;
    const int lane = tid & 31;
    const int w    = tid >> 5;
    const int g    = lane >> 2;
    const int t    = lane & 3;
    const int bh   = blockIdx.y;
    const int qb   = (gridDim.x - 1) - blockIdx.x;   // heavy blocks first
    const int qblk = qb * 128;

    const float* Qg = Q + (size_t)bh * SEQ * DH;
    const float* Kg = K + (size_t)bh * SEQ * DH;
    const float* Vg = V + (size_t)bh * SEQ * DH;

    // ---- stage Q: tile is contiguous 128*64 floats; flat coalesced ----
    {
        const float* src = Qg + (size_t)qblk * DH;
        #pragma unroll
        for (int j = 0; j < 16; j++) {
            const int f = (tid + j * 128) * 4;
            const int row = f >> 6, d = f & 63;
            float4 v = *(const float4*)(src + f);
            float* dst = Qs + row * AQ_LD + d;
            dst[0] = tf32r(v.x * 0.125f);
            dst[1] = tf32r(v.y * 0.125f);
            dst[2] = tf32r(v.z * 0.125f);
            dst[3] = tf32r(v.w * 0.125f);
        }
    }

    float o[2][8][4];
    #pragma unroll
    for (int mt = 0; mt < 2; mt++)
        #pragma unroll
        for (int nt = 0; nt < 8; nt++)
            #pragma unroll
            for (int e = 0; e < 4; e++) o[mt][nt][e] = 0.f;
    float mrow[2][2] = {{-1e30f, -1e30f}, {-1e30f, -1e30f}};
    float lrow[2][2] = {{0.f, 0.f}, {0.f, 0.f}};

    const int ntiles = 2 * qb + 2;
    const int wrow   = qblk + w * 32;
    const int wmax   = wrow + 31;

    for (int kt = 0; kt < ntiles; kt++) {
        const int kbase = kt * 64;
        __syncthreads();
        // ---- stage K/V tiles (contiguous 64*64 floats), coalesced LDG.128 + STS.128 ----
        {
            const float* ksrc = Kg + (size_t)kbase * DH;
            const float* vsrc = Vg + (size_t)kbase * DH;
            #pragma unroll
            for (int j = 0; j < 8; j++) {
                const int f = (tid + j * 128) * 4;
                const int key = f >> 6, d = f & 63;
                float4 kv = *(const float4*)(ksrc + f);
                float* kd = Ks + key * AK_LD + d;
                kd[0] = tf32r(kv.x); kd[1] = tf32r(kv.y);
                kd[2] = tf32r(kv.z); kd[3] = tf32r(kv.w);
                float4 vv = *(const float4*)(vsrc + f);
                float* vd = Vs + key * AV_LD + d;
                vd[0] = tf32r(vv.x); vd[1] = tf32r(vv.y);
                vd[2] = tf32r(vv.z); vd[3] = tf32r(vv.w);
            }
        }
        __syncthreads();
        if (kbase > wmax) continue;

        // ---- S = Q K^T ----
        float s[2][8][4];
        #pragma unroll
        for (int mt = 0; mt < 2; mt++)
            #pragma unroll
            for (int nt = 0; nt < 8; nt++)
                #pragma unroll
                for (int e = 0; e < 4; e++) s[mt][nt][e] = 0.f;

        #pragma unroll
        for (int ks = 0; ks < 8; ks++) {
            uint32_t af[2][4];
            #pragma unroll
            for (int mt = 0; mt < 2; mt++) {
                const int r0 = w * 32 + mt * 16 + g;
                af[mt][0] = __float_as_uint(Qs[(r0    ) * AQ_LD + ks*8 + t    ]);
                af[mt][1] = __float_as_uint(Qs[(r0 + 8) * AQ_LD + ks*8 + t    ]);
                af[mt][2] = __float_as_uint(Qs[(r0    ) * AQ_LD + ks*8 + t + 4]);
                af[mt][3] = __float_as_uint(Qs[(r0 + 8) * AQ_LD + ks*8 + t + 4]);
            }
            #pragma unroll
            for (int nt = 0; nt < 8; nt++) {
                uint32_t b0 = __float_as_uint(Ks[(nt*8 + g) * AK_LD + ks*8 + t    ]);
                uint32_t b1 = __float_as_uint(Ks[(nt*8 + g) * AK_LD + ks*8 + t + 4]);
                mma_tf32(s[0][nt], af[0], b0, b1);
                mma_tf32(s[1][nt], af[1], b0, b1);
            }
        }

        // ---- causal mask ----
        if (kbase + 63 > wrow) {
            #pragma unroll
            for (int mt = 0; mt < 2; mt++) {
                const int r0 = wrow + mt * 16 + g;
                const int r1 = r0 + 8;
                #pragma unroll
                for (int nt = 0; nt < 8; nt++) {
                    const int key = kbase + nt * 8 + 2 * t;
                    if (key     > r0) s[mt][nt][0] = -1e30f;
                    if (key + 1 > r0) s[mt][nt][1] = -1e30f;
                    if (key     > r1) s[mt][nt][2] = -1e30f;
                    if (key + 1 > r1) s[mt][nt][3] = -1e30f;
                }
            }
        }

        // ---- online softmax ----
        #pragma unroll
        for (int mt = 0; mt < 2; mt++) {
            float mx0 = -1e30f, mx1 = -1e30f;
            #pragma unroll
            for (int nt = 0; nt < 8; nt++) {
                mx0 = fmaxf(mx0, fmaxf(s[mt][nt][0], s[mt][nt][1]));
                mx1 = fmaxf(mx1, fmaxf(s[mt][nt][2], s[mt][nt][3]));
            }
            mx0 = fmaxf(mx0, __shfl_xor_sync(0xFFFFFFFFu, mx0, 1));
            mx0 = fmaxf(mx0, __shfl_xor_sync(0xFFFFFFFFu, mx0, 2));
            mx1 = fmaxf(mx1, __shfl_xor_sync(0xFFFFFFFFu, mx1, 1));
            mx1 = fmaxf(mx1, __shfl_xor_sync(0xFFFFFFFFu, mx1, 2));
            const float mn0 = fmaxf(mrow[mt][0], mx0);
            const float mn1 = fmaxf(mrow[mt][1], mx1);
            const float c0 = __expf(mrow[mt][0] - mn0);
            const float c1 = __expf(mrow[mt][1] - mn1);
            lrow[mt][0] *= c0; lrow[mt][1] *= c1;
            #pragma unroll
            for (int nt = 0; nt < 8; nt++) {
                o[mt][nt][0] *= c0; o[mt][nt][1] *= c0;
                o[mt][nt][2] *= c1; o[mt][nt][3] *= c1;
            }
            mrow[mt][0] = mn0; mrow[mt][1] = mn1;
            float rs0 = 0.f, rs1 = 0.f;
            #pragma unroll
            for (int nt = 0; nt < 8; nt++) {
                s[mt][nt][0] = __expf(s[mt][nt][0] - mn0);
                s[mt][nt][1] = __expf(s[mt][nt][1] - mn0);
                s[mt][nt][2] = __expf(s[mt][nt][2] - mn1);
                s[mt][nt][3] = __expf(s[mt][nt][3] - mn1);
                rs0 += s[mt][nt][0] + s[mt][nt][1];
                rs1 += s[mt][nt][2] + s[mt][nt][3];
            }
            rs0 += __shfl_xor_sync(0xFFFFFFFFu, rs0, 1);
            rs0 += __shfl_xor_sync(0xFFFFFFFFu, rs0, 2);
            rs1 += __shfl_xor_sync(0xFFFFFFFFu, rs1, 1);
            rs1 += __shfl_xor_sync(0xFFFFFFFFu, rs1, 2);
            lrow[mt][0] += rs0; lrow[mt][1] += rs1;
        }

        // ---- O += P V : transpose P frags via shfl, mma against V (row-major) ----
        const int src1 = (g << 2) | (t >> 1);
        const int src2 = src1 + 2;
        const bool odd = (t & 1) != 0;
        #pragma unroll
        for (int ks = 0; ks < 8; ks++) {
            uint32_t af[2][4];
            #pragma unroll
            for (int mt = 0; mt < 2; mt++) {
                float e0 = __shfl_sync(0xFFFFFFFFu, s[mt][ks][0], src1);
                float e1 = __shfl_sync(0xFFFFFFFFu, s[mt][ks][1], src1);
                float e2 = __shfl_sync(0xFFFFFFFFu, s[mt][ks][2], src1);
                float e3 = __shfl_sync(0xFFFFFFFFu, s[mt][ks][3], src1);
                float f0 = __shfl_sync(0xFFFFFFFFu, s[mt][ks][0], src2);
                float f1 = __shfl_sync(0xFFFFFFFFu, s[mt][ks][1], src2);
                float f2 = __shfl_sync(0xFFFFFFFFu, s[mt][ks][2], src2);
                float f3 = __shfl_sync(0xFFFFFFFFu, s[mt][ks][3], src2);
                af[mt][0] = cvt_tf32(odd ? e1 : e0);
                af[mt][1] = cvt_tf32(odd ? e3 : e2);
                af[mt][2] = cvt_tf32(odd ? f1 : f0);
                af[mt][3] = cvt_tf32(odd ? f3 : f2);
            }
            #pragma unroll
            for (int dnt = 0; dnt < 8; dnt++) {
                uint32_t b0 = __float_as_uint(Vs[(ks*8 + t    ) * AV_LD + dnt*8 + g]);
                uint32_t b1 = __float_as_uint(Vs[(ks*8 + t + 4) * AV_LD + dnt*8 + g]);
                mma_tf32(o[0][dnt], af[0], b0, b1);
                mma_tf32(o[1][dnt], af[1], b0, b1);
            }
        }
    }

    // ---- normalize + write [b][t][h*64+dh] ----
    const int b = bh >> 4, h = bh & 15;
    #pragma unroll
    for (int mt = 0; mt < 2; mt++) {
        const float i0 = 1.f / lrow[mt][0];
        const float i1 = 1.f / lrow[mt][1];
        const int r0 = wrow + mt * 16 + g;
        const int r1 = r0 + 8;
        #pragma unroll
        for (int dnt = 0; dnt < 8; dnt++) {
            const int col = h * 64 + dnt * 8 + 2 * t;
            *(float2*)(O + ((size_t)(b * SEQ + r0)) * DM + col) =
                make_float2(o[mt][dnt][0] * i0, o[mt][dnt][1] * i0);
            *(float2*)(O + ((size_t)(b * SEQ + r1)) * DM + col) =
                make_float2(o[mt][dnt][2] * i1, o[mt][dnt][3] * i1);
        }
    }
}

// ---------------- launcher ----------------
extern "C" void kernel_launch(void* const* d_in, const int* in_sizes, int n_in,
                              void* d_out, int out_size)
{
    const float* x  = (const float*)d_in[0];
    const float* Wq = (const float*)d_in[1];
    const float* bq = (const float*)d_in[2];
    const float* Wk = (const float*)d_in[3];
    const float* bk = (const float*)d_in[4];
    const float* Wv = (const float*)d_in[5];
    const float* bv = (const float*)d_in[6];
    const float* Wo = (const float*)d_in[7];
    const float* bo = (const float*)d_in[8];
    float* out = (float*)d_out;

    float *qp, *kp, *vp, *ap;
    cudaGetSymbolAddress((void**)&qp, g_Q);
    cudaGetSymbolAddress((void**)&kp, g_K);
    cudaGetSymbolAddress((void**)&vp, g_V);
    cudaGetSymbolAddress((void**)&ap, g_A);

    cudaFuncSetAttribute(gemm_qkv_kernel, cudaFuncAttributeMaxDynamicSharedMemorySize, GSMEM_BYTES);
    cudaFuncSetAttribute(gemm_o_kernel,  cudaFuncAttributeMaxDynamicSharedMemorySize, GSMEM_BYTES);
    cudaFuncSetAttribute(attn_mma_kernel, cudaFuncAttributeMaxDynamicSharedMemorySize, A_SMEM_BYTES);

    dim3 gq(DM / GN, MROWS / GM, 3);   // (8, 32, 3) -> 768 CTAs
    gemm_qkv_kernel<<<gq, 256, GSMEM_BYTES>>>(x, Wq, bq, Wk, bk, Wv, bv, qp, kp, vp);

    attn_mma_kernel<<<dim3(SEQ / 128, BATCH * NH), 128, A_SMEM_BYTES>>>(qp, kp, vp, ap);

    dim3 gg(DM / GN, MROWS / GM);      // (8, 32)
    gemm_o_kernel<<<gg, 256, GSMEM_BYTES>>>(ap, Wo, bo, out);
}